// round 6
// baseline (speedup 1.0000x reference)
#include <cuda_runtime.h>
#include <math.h>

// LSTM: B=128, T=1024, D=512, H=512.
// Persistent kernel: 128 CTAs = 2 batch tiles (64 rows) x 64 h-col tiles (8 h cols -> 32 gate cols).
// W slice resident in SMEM as float4 (4 packed gate cols); A duplicated-pair float4 covers 2 k per LDS.128.
// Per-thread tile: 2 rows x 2 f32x2 col-pairs -> 4 LDS.128 + 8 FMA2 per 2 k.

#define NB 128
#define NT 1024
#define ND 512
#define NH 512
#define K_TOT 1024
#define GRID 128
#define THREADS 256
#define ROWS_CTA 64
#define KC 64
#define A_PITCH 33   // float4 per row (64 k / 2), padded
#define Y_PITCH 36   // floats per row (32 cols), 16B-aligned pitch

__device__ volatile unsigned g_sense;
__device__ unsigned g_count;
__device__ float g_hbuf[2][NB * NH];

__device__ __forceinline__ unsigned long long pack2(float lo, float hi) {
    unsigned long long r;
    asm("mov.b64 %0, {%1,%2};" : "=l"(r) : "f"(lo), "f"(hi));
    return r;
}
__device__ __forceinline__ void unpack2(unsigned long long v, float& lo, float& hi) {
    asm("mov.b64 {%0,%1}, %2;" : "=f"(lo), "=f"(hi) : "l"(v));
}
#define FMA2(acc, a, w) \
    asm("fma.rn.f32x2 %0, %1, %2, %0;" : "+l"(acc) : "l"(a), "l"(w))

__device__ __forceinline__ float sigf(float x) { return 1.0f / (1.0f + expf(-x)); }

__global__ void __launch_bounds__(THREADS, 1) lstm_persistent(
    const float* __restrict__ obs, const float* __restrict__ Wi,
    const float* __restrict__ Wh, const float* __restrict__ bv,
    const float* __restrict__ c0, const float* __restrict__ h0,
    float* __restrict__ out, int out_size)
{
    extern __shared__ char smraw[];
    // W4: float4[1024][8]          131072 B  (cols 4j..4j+3 of this CTA's 32 gate cols)
    // A4: float4[64][A_PITCH]       33792 B  (a_k,a_k,a_{k+1},a_{k+1}) per entry
    // Yf: float [64][Y_PITCH]        9216 B  (gate pre-activations for combine)
    float4* W4 = (float4*)smraw;
    float4* A4 = (float4*)(smraw + 131072);
    float*  Yf = (float*)(smraw + 131072 + 33792);

    const int tid = threadIdx.x;
    const int tx3 = tid & 7;        // col-group: 4 gate cols 4*tx3..4*tx3+3
    const int tyr = tid >> 3;       // row-group: rows 2*tyr, 2*tyr+1
    const int r0 = 2 * tyr, r1 = 2 * tyr + 1;
    const int bi = blockIdx.x >> 6;
    const int hj = blockIdx.x & 63;
    const int row0 = bi * ROWS_CTA;
    const int hcol0 = hj * 8;

    // ---- one-time: fill W4 (rows 0..511 from Wi, 512..1023 from Wh) ----
    // local col c -> global gate col: ((c>>3)<<9) + hcol0 + (c&7); entry j covers 4 consecutive global cols
    for (int idx = tid; idx < K_TOT * 8; idx += THREADS) {
        int k = idx >> 3, j = idx & 7;
        int gbase = ((j >> 1) << 9) + hcol0 + ((j & 1) << 2);
        float4 v;
        if (k < ND) v = *(const float4*)&Wi[k * 2048 + gbase];
        else        v = *(const float4*)&Wh[(k - ND) * 2048 + gbase];
        W4[idx] = v;
    }

    // bias for this thread's 4 cols (2 f32x2 pairs)
    const int gcb = ((tx3 >> 1) << 9) + hcol0 + ((tx3 & 1) << 2);
    const unsigned long long bias_p0 = pack2(bv[gcb + 0], bv[gcb + 1]);
    const unsigned long long bias_p1 = pack2(bv[gcb + 2], bv[gcb + 3]);

    // elementwise ownership: two (row, hcol) pairs per thread; c kept in registers
    const int p0 = tid, p1 = tid + 256;
    const int r_p0 = p0 >> 3, h_p0 = p0 & 7;
    const int r_p1 = p1 >> 3, h_p1 = p1 & 7;
    const int gi0 = (row0 + r_p0) * NH + hcol0 + h_p0;
    const int gi1 = (row0 + r_p1) * NH + hcol0 + h_p1;
    float cs0 = c0[gi0], cs1 = c0[gi1];

    __syncthreads();

    const ulonglong2* a0p = (const ulonglong2*)(A4 + r0 * A_PITCH);
    const ulonglong2* a1p = (const ulonglong2*)(A4 + r1 * A_PITCH);
    float2 rg[8];

    for (int t = 0; t < NT; ++t) {
        const float* hsrc = (t == 0) ? h0 : (const float*)g_hbuf[t & 1];
        unsigned long long acc00 = bias_p0, acc01 = bias_p1;
        unsigned long long acc10 = bias_p0, acc11 = bias_p1;

        // prologue: load K-chunk 0 (pure obs) into registers (float2 = 2 k values)
        #pragma unroll
        for (int i = 0; i < 8; ++i) {
            int idx = tid + (i << 8);          // over 2048 float4 slots
            int r = idx >> 5, k2 = idx & 31;
            rg[i] = *(const float2*)&obs[((row0 + r) * NT + t) * ND + 2 * k2];
        }

        for (int ch = 0; ch < 16; ++ch) {
            __syncthreads();
            // store staged chunk to SMEM, duplicated pairs for f32x2 broadcast
            #pragma unroll
            for (int i = 0; i < 8; ++i) {
                int idx = tid + (i << 8);
                int r = idx >> 5, k2 = idx & 31;
                A4[r * A_PITCH + k2] = make_float4(rg[i].x, rg[i].x, rg[i].y, rg[i].y);
            }
            __syncthreads();
            // prefetch next chunk (chunks are homogeneous: ch<8 obs, ch>=8 h)
            if (ch < 15) {
                const int chn = ch + 1;
                if (chn < 8) {
                    const int kg0 = chn * KC;
                    #pragma unroll
                    for (int i = 0; i < 8; ++i) {
                        int idx = tid + (i << 8);
                        int r = idx >> 5, k2 = idx & 31;
                        rg[i] = *(const float2*)&obs[((row0 + r) * NT + t) * ND + kg0 + 2 * k2];
                    }
                } else {
                    const int kg0 = chn * KC - ND;
                    #pragma unroll
                    for (int i = 0; i < 8; ++i) {
                        int idx = tid + (i << 8);
                        int r = idx >> 5, k2 = idx & 31;
                        rg[i] = __ldcg((const float2*)(hsrc + (row0 + r) * NH + kg0 + 2 * k2));
                    }
                }
            }
            // compute: 32 k2-iters (64 k), 4 LDS.128 + 8 FMA2 each
            const ulonglong2* wp = (const ulonglong2*)(W4 + ch * KC * 8) + tx3;
            #pragma unroll 4
            for (int k2 = 0; k2 < 32; ++k2) {
                ulonglong2 w0 = wp[(2 * k2) * 8];
                ulonglong2 w1 = wp[(2 * k2 + 1) * 8];
                ulonglong2 a0 = a0p[k2];
                ulonglong2 a1 = a1p[k2];
                FMA2(acc00, a0.x, w0.x); FMA2(acc01, a0.x, w0.y);
                FMA2(acc10, a1.x, w0.x); FMA2(acc11, a1.x, w0.y);
                FMA2(acc00, a0.y, w1.x); FMA2(acc01, a0.y, w1.y);
                FMA2(acc10, a1.y, w1.x); FMA2(acc11, a1.y, w1.y);
            }
        }

        // publish gate pre-activations: one float4 per row = cols 4*tx3..4*tx3+3
        {
            float l0, h0v, l1, h1v;
            unpack2(acc00, l0, h0v); unpack2(acc01, l1, h1v);
            ((float4*)(Yf + r0 * Y_PITCH))[tx3] = make_float4(l0, h0v, l1, h1v);
            unpack2(acc10, l0, h0v); unpack2(acc11, l1, h1v);
            ((float4*)(Yf + r1 * Y_PITCH))[tx3] = make_float4(l0, h0v, l1, h1v);
        }
        __syncthreads();

        float hn0, hn1;
        {
            float iv = Yf[r_p0 * Y_PITCH + h_p0];
            float fv = Yf[r_p0 * Y_PITCH + 8 + h_p0];
            float gv = Yf[r_p0 * Y_PITCH + 16 + h_p0];
            float ov = Yf[r_p0 * Y_PITCH + 24 + h_p0];
            cs0 = sigf(fv) * cs0 + sigf(iv) * tanhf(gv);
            hn0 = sigf(ov) * tanhf(cs0);
        }
        {
            float iv = Yf[r_p1 * Y_PITCH + h_p1];
            float fv = Yf[r_p1 * Y_PITCH + 8 + h_p1];
            float gv = Yf[r_p1 * Y_PITCH + 16 + h_p1];
            float ov = Yf[r_p1 * Y_PITCH + 24 + h_p1];
            cs1 = sigf(fv) * cs1 + sigf(iv) * tanhf(gv);
            hn1 = sigf(ov) * tanhf(cs1);
        }

        // h for next step + contexts output
        float* hdst = g_hbuf[(t + 1) & 1];
        hdst[gi0] = hn0;
        hdst[gi1] = hn1;
        out[((row0 + r_p0) * NT + t) * NH + hcol0 + h_p0] = hn0;
        out[((row0 + r_p1) * NT + t) * NH + hcol0 + h_p1] = hn1;
        if (t == NT - 1) {
            int base = NB * NT * NH;
            if (out_size >= base + 2 * NB * NH) {
                out[base + gi0] = cs0;              // cT
                out[base + gi1] = cs1;
                out[base + NB * NH + gi0] = hn0;    // hT
                out[base + NB * NH + gi1] = hn1;
            }
        }

        // device-wide sense-reversal barrier
        __threadfence();
        __syncthreads();
        if (tid == 0) {
            const unsigned target = (unsigned)((t & 1) ^ 1);
            if (atomicAdd(&g_count, 1u) == GRID - 1) {
                g_count = 0;
                __threadfence();
                g_sense = target;
            } else {
                while (g_sense != target) { }
                __threadfence();
            }
        }
        __syncthreads();
    }
}

extern "C" void kernel_launch(void* const* d_in, const int* in_sizes, int n_in,
                              void* d_out, int out_size)
{
    const float* obs = (const float*)d_in[0];
    const float* Wi  = (const float*)d_in[1];
    const float* Wh  = (const float*)d_in[2];
    const float* bv  = (const float*)d_in[3];
    const float* c0  = (const float*)d_in[4];
    const float* h0  = (const float*)d_in[5];

    const int smem_bytes = 131072 + 33792 + 9216;  // 174,080 B
    cudaFuncSetAttribute(lstm_persistent,
                         cudaFuncAttributeMaxDynamicSharedMemorySize, smem_bytes);
    lstm_persistent<<<GRID, THREADS, smem_bytes>>>(obs, Wi, Wh, bv, c0, h0,
                                                   (float*)d_out, out_size);
}

// round 8
// speedup vs baseline: 1.4479x; 1.4479x over previous
#include <cuda_runtime.h>
#include <cuda_bf16.h>
#include <stdint.h>

// LSTM B=128,T=1024,D=512,H=512 via portable mma.sync bf16x3 (sm_103 baseline target).
#define SWZ(x) ((x) ^ (((x) >> 3) & 0x70))

__device__ __align__(128) unsigned short g_obs_hi[67108864];  // [t][b][d]
__device__ __align__(128) unsigned short g_obs_lo[67108864];
__device__ __align__(128) unsigned char  g_wt[8388608];       // [cta 64][hi 64KB | lo 64KB]
__device__ __align__(128) unsigned short g_hh[2][65536];      // [phase][b][h]
__device__ __align__(128) unsigned short g_hl[2][65536];
__device__ volatile unsigned g_sense;
__device__ unsigned g_count;

__device__ __forceinline__ uint32_t smem_u32(const void* p) {
    uint32_t a;
    asm("{ .reg .u64 t; cvta.to.shared.u64 t, %1; cvt.u32.u64 %0, t; }" : "=r"(a) : "l"(p));
    return a;
}
#define CPA(d, s) asm volatile("cp.async.cg.shared.global [%0], [%1], 16;" :: "r"(d), "l"(s) : "memory")
#define CPCOMMIT() asm volatile("cp.async.commit_group;" ::: "memory")
#define CPWAIT(n)  asm volatile("cp.async.wait_group %0;" :: "n"(n) : "memory")
#define LDM4(r, a) \
    asm volatile("ldmatrix.sync.aligned.m8n8.x4.shared.b16 {%0,%1,%2,%3}, [%4];" \
        : "=r"((r)[0]), "=r"((r)[1]), "=r"((r)[2]), "=r"((r)[3]) : "r"(a) : "memory")
#define LDM4T(r, a) \
    asm volatile("ldmatrix.sync.aligned.m8n8.x4.trans.shared.b16 {%0,%1,%2,%3}, [%4];" \
        : "=r"((r)[0]), "=r"((r)[1]), "=r"((r)[2]), "=r"((r)[3]) : "r"(a) : "memory")
#define MMA(d, a, b0, b1) \
    asm volatile("mma.sync.aligned.m16n8k16.row.col.f32.bf16.bf16.f32 " \
        "{%0,%1,%2,%3},{%4,%5,%6,%7},{%8,%9},{%0,%1,%2,%3};" \
        : "+f"((d)[0]), "+f"((d)[1]), "+f"((d)[2]), "+f"((d)[3]) \
        : "r"((a)[0]), "r"((a)[1]), "r"((a)[2]), "r"((a)[3]), "r"(b0), "r"(b1))

__device__ __forceinline__ void bsplit(float v, unsigned short& h, unsigned short& l) {
    __nv_bfloat16 bh = __float2bfloat16(v);
    __nv_bfloat16 bl = __float2bfloat16(v - __bfloat162float(bh));
    h = *(unsigned short*)&bh; l = *(unsigned short*)&bl;
}

// ---------------- prep kernels ----------------
// W smem layout (per CTA): [k 0..1023][n 0..31], off = k*64 + ((n>>3 ^ ((k>>1)&3))<<4) + ((n&7)<<1)
__global__ void pack_w(const float* __restrict__ Wi, const float* __restrict__ Wh) {
    int c = blockIdx.x;
    unsigned char* base = g_wt + (size_t)c * 131072;
    for (int e = threadIdx.x; e < 32768; e += 256) {
        int k = e >> 5, n = e & 31;
        int col = (n >> 3) * 512 + c * 8 + (n & 7);
        float v = (k < 512) ? Wi[k * 2048 + col] : Wh[(k - 512) * 2048 + col];
        unsigned short h, l; bsplit(v, h, l);
        int off = k * 64 + ((((n >> 3)) ^ ((k >> 1) & 3)) << 4) + ((n & 7) << 1);
        *(unsigned short*)(base + off) = h;
        *(unsigned short*)(base + 65536 + off) = l;
    }
}
__global__ void conv_obs(const float* __restrict__ obs) {
    size_t g = (size_t)blockIdx.x * 256 + threadIdx.x;   // 16,777,216
    int d4 = (int)(g & 127); size_t bt = g >> 7;
    int b = (int)(bt >> 10), t = (int)(bt & 1023);
    float4 v = *(const float4*)&obs[(((size_t)b * 1024 + t) * 512) + d4 * 4];
    unsigned short h0,h1,h2,h3,l0,l1,l2,l3;
    bsplit(v.x,h0,l0); bsplit(v.y,h1,l1); bsplit(v.z,h2,l2); bsplit(v.w,h3,l3);
    size_t o = ((size_t)t * 128 + b) * 512 + d4 * 4;
    *(ushort4*)&g_obs_hi[o] = make_ushort4(h0,h1,h2,h3);
    *(ushort4*)&g_obs_lo[o] = make_ushort4(l0,l1,l2,l3);
}
__global__ void pack_h0(const float* __restrict__ h0p) {
    int g = blockIdx.x * 256 + threadIdx.x;  // 65536
    unsigned short h, l; bsplit(h0p[g], h, l);
    g_hh[0][g] = h; g_hl[0][g] = l;
}

// ---------------- recurrent kernel ----------------
// stage A chunk [128 b][64 k] bf16 hi+lo into SW128-swizzled smem buffer
__device__ __forceinline__ void stage_chunk(uint32_t dst, int t, int ch, int tid) {
    const unsigned short *bh, *bl; int koff;
    if (ch < 8) { bh = g_obs_hi + (size_t)t * 65536; bl = g_obs_lo + (size_t)t * 65536; koff = ch * 64; }
    else        { int p = t & 1; bh = g_hh[p]; bl = g_hl[p]; koff = (ch - 8) * 64; }
    #pragma unroll
    for (int i = 0; i < 4; i++) {
        int g = i * 256 + tid; int r = g >> 3, seg = g & 7;
        uint32_t d = dst + SWZ(r * 128 + seg * 16);
        CPA(d, bh + r * 512 + koff + seg * 8);
        CPA(d + 16384, bl + r * 512 + koff + seg * 8);
    }
}

__global__ void __launch_bounds__(256, 1) lstm_rec(
    const float* __restrict__ bv, const float* __restrict__ c0,
    float* __restrict__ out, int out_size)
{
    extern __shared__ char sm[];  // [W hi 64K | W lo 64K][Abuf0 hi16K lo16K][Abuf1 hi16K lo16K]
    const int tid = threadIdx.x, warp = tid >> 5, lane = tid & 31;
    const int c = blockIdx.x, hc0 = c * 8;
    const uint32_t smW = smem_u32(sm), smA = smW + 131072;

    // load resident W (128KB)
    const unsigned char* wsrc = g_wt + (size_t)c * 131072;
    for (int i = tid; i < 8192; i += 256) CPA(smW + i * 16, wsrc + i * 16);
    CPCOMMIT(); CPWAIT(0);
    __syncthreads();

    // per-thread ownership: rows r0,(r0+8); cols j0,j0+1 (n = 8*gate + j)
    const int r0 = (warp << 4) + (lane >> 2);
    const int j0 = 2 * (lane & 3);
    float bb[4][2];
    #pragma unroll
    for (int g = 0; g < 4; g++) {
        bb[g][0] = bv[g * 512 + hc0 + j0];
        bb[g][1] = bv[g * 512 + hc0 + j0 + 1];
    }
    float cs[4];   // [rh*2+cp] : rows r0,r0+8 x cols j0,j0+1
    #pragma unroll
    for (int rh = 0; rh < 2; rh++)
        #pragma unroll
        for (int cp = 0; cp < 2; cp++)
            cs[rh * 2 + cp] = c0[(r0 + rh * 8) * 512 + hc0 + j0 + cp];

    stage_chunk(smA, 0, 0, tid); CPCOMMIT();
    stage_chunk(smA + 32768, 0, 1, tid); CPCOMMIT();

    const int m0 = warp << 4;
    const int hseg = (lane >> 4) * 16;       // A k-halves
    const int arow = m0 + (lane & 15);
    const int brow_l = lane & 15;            // B k-row within k16
    const int bgsel = lane >> 4;             // B n-half

    for (int t = 0; t < 1024; t++) {
        float acc[4][4];
        #pragma unroll
        for (int i = 0; i < 4; i++)
            #pragma unroll
            for (int j = 0; j < 4; j++) acc[i][j] = 0.f;

        for (int ch = 0; ch < 16; ch++) {
            const int b = ch & 1;
            CPWAIT(1);
            __syncthreads();
            const uint32_t Ah = smA + b * 32768, Al = Ah + 16384;
            #pragma unroll
            for (int ks = 0; ks < 4; ks++) {
                uint32_t ah[4], al[4], bh0[4], bh1[4], bl0[4], bl1[4];
                uint32_t aoff = SWZ(arow * 128 + ks * 32 + hseg);
                LDM4(ah, Ah + aoff);
                LDM4(al, Al + aoff);
                int krow = ch * 64 + ks * 16 + brow_l;
                uint32_t bsw = (krow >> 1) & 3;
                uint32_t ba0 = smW + krow * 64 + ((bgsel ^ bsw) << 4);
                uint32_t ba1 = smW + krow * 64 + (((2 + bgsel) ^ bsw) << 4);
                LDM4T(bh0, ba0); LDM4T(bh1, ba1);
                LDM4T(bl0, ba0 + 65536); LDM4T(bl1, ba1 + 65536);
                MMA(acc[0], ah, bh0[0], bh0[1]); MMA(acc[1], ah, bh0[2], bh0[3]);
                MMA(acc[2], ah, bh1[0], bh1[1]); MMA(acc[3], ah, bh1[2], bh1[3]);
                MMA(acc[0], ah, bl0[0], bl0[1]); MMA(acc[1], ah, bl0[2], bl0[3]);
                MMA(acc[2], ah, bl1[0], bl1[1]); MMA(acc[3], ah, bl1[2], bl1[3]);
                MMA(acc[0], al, bh0[0], bh0[1]); MMA(acc[1], al, bh0[2], bh0[3]);
                MMA(acc[2], al, bh1[0], bh1[1]); MMA(acc[3], al, bh1[2], bh1[3]);
            }
            __syncthreads();
            int ch2 = ch + 2, t2 = t;
            if (ch2 > 15) { ch2 -= 16; t2++; }
            if (t2 < 1024) stage_chunk(smA + b * 32768, t2, ch2, tid);
            CPCOMMIT();
        }

        // epilogue: gates are register-local (nt = gate, same lane offsets)
        const int pn = (t + 1) & 1;
        #pragma unroll
        for (int rh = 0; rh < 2; rh++) {
            const int r = r0 + rh * 8;
            float hv[2];
            #pragma unroll
            for (int cp = 0; cp < 2; cp++) {
                const int idx = rh * 2 + cp;
                float iv = acc[0][idx] + bb[0][cp];
                float fv = acc[1][idx] + bb[1][cp];
                float gv = acc[2][idx] + bb[2][cp];
                float ov = acc[3][idx] + bb[3][cp];
                float si = 1.f / (1.f + __expf(-iv));
                float sf = 1.f / (1.f + __expf(-fv));
                float so = 1.f / (1.f + __expf(-ov));
                float tg = 1.f - 2.f / (__expf(2.f * gv) + 1.f);
                float cn = sf * cs[idx] + si * tg;
                cs[idx] = cn;
                float tc = 1.f - 2.f / (__expf(2.f * cn) + 1.f);
                hv[cp] = so * tc;
            }
            *(float2*)&out[((size_t)r * 1024 + t) * 512 + hc0 + j0] = make_float2(hv[0], hv[1]);
            unsigned short h0b, l0b, h1b, l1b;
            bsplit(hv[0], h0b, l0b); bsplit(hv[1], h1b, l1b);
            *(ushort2*)&g_hh[pn][r * 512 + hc0 + j0] = make_ushort2(h0b, h1b);
            *(ushort2*)&g_hl[pn][r * 512 + hc0 + j0] = make_ushort2(l0b, l1b);
            if (t == 1023 && out_size >= 67108864 + 131072) {
                out[67108864 + r * 512 + hc0 + j0]     = cs[rh * 2 + 0];
                out[67108864 + r * 512 + hc0 + j0 + 1] = cs[rh * 2 + 1];
                out[67108864 + 65536 + r * 512 + hc0 + j0]     = hv[0];
                out[67108864 + 65536 + r * 512 + hc0 + j0 + 1] = hv[1];
            }
        }

        // device-wide sense-reversal barrier (64 CTAs)
        __threadfence();
        __syncthreads();
        if (tid == 0) {
            const unsigned target = (unsigned)((t & 1) ^ 1);
            if (atomicAdd(&g_count, 1u) == 63) {
                g_count = 0; __threadfence(); g_sense = target;
            } else {
                while (g_sense != target) { } __threadfence();
            }
        }
        __syncthreads();
    }
}

extern "C" void kernel_launch(void* const* d_in, const int* in_sizes, int n_in,
                              void* d_out, int out_size)
{
    const float* obs = (const float*)d_in[0];
    const float* Wi  = (const float*)d_in[1];
    const float* Wh  = (const float*)d_in[2];
    const float* bv  = (const float*)d_in[3];
    const float* c0  = (const float*)d_in[4];
    const float* h0  = (const float*)d_in[5];

    pack_w<<<64, 256>>>(Wi, Wh);
    conv_obs<<<65536, 256>>>(obs);
    pack_h0<<<256, 256>>>(h0);

    const int smem = 196608;  // 128K W + 64K A double-buffer
    cudaFuncSetAttribute(lstm_rec, cudaFuncAttributeMaxDynamicSharedMemorySize, smem);
    lstm_rec<<<64, 256, smem>>>(bv, c0, (float*)d_out, out_size);
}

// round 10
// speedup vs baseline: 3.1802x; 2.1964x over previous
#include <cuda_runtime.h>
#include <cuda_bf16.h>
#include <stdint.h>

// LSTM B=128,T=1024,D=512,H=512 via portable mma.sync bf16x3.
// Grid 128 = 2 batch-tiles (64 rows) x 64 h-tiles (8 h-cols -> 32 gate cols).
// W resident in SMEM (128KB); A=[x_t|h] streamed in 16 K=64 chunks, 4-buffer
// single-sync cp.async pipeline. Gate-interleaved B columns keep epilogue register-local.
#define SWZ(x) ((x) ^ (((x) >> 3) & 0x70))

__device__ __align__(128) unsigned short g_obs_hi[67108864];  // [t][b][d]
__device__ __align__(128) unsigned short g_obs_lo[67108864];
__device__ __align__(128) unsigned char  g_wt[8388608];       // [htile 64][hi 64KB | lo 64KB]
__device__ __align__(128) unsigned short g_hh[2][65536];      // [phase][b][h]
__device__ __align__(128) unsigned short g_hl[2][65536];
__device__ volatile unsigned g_sense;
__device__ unsigned g_count;

__device__ __forceinline__ uint32_t smem_u32(const void* p) {
    uint32_t a;
    asm("{ .reg .u64 t; cvta.to.shared.u64 t, %1; cvt.u32.u64 %0, t; }" : "=r"(a) : "l"(p));
    return a;
}
#define CPA(d, s) asm volatile("cp.async.cg.shared.global [%0], [%1], 16;" :: "r"(d), "l"(s) : "memory")
#define CPCOMMIT() asm volatile("cp.async.commit_group;" ::: "memory")
#define CPWAIT(n)  asm volatile("cp.async.wait_group %0;" :: "n"(n) : "memory")
#define LDM4(r, a) \
    asm volatile("ldmatrix.sync.aligned.m8n8.x4.shared.b16 {%0,%1,%2,%3}, [%4];" \
        : "=r"((r)[0]), "=r"((r)[1]), "=r"((r)[2]), "=r"((r)[3]) : "r"(a) : "memory")
#define LDM4T(r, a) \
    asm volatile("ldmatrix.sync.aligned.m8n8.x4.trans.shared.b16 {%0,%1,%2,%3}, [%4];" \
        : "=r"((r)[0]), "=r"((r)[1]), "=r"((r)[2]), "=r"((r)[3]) : "r"(a) : "memory")
#define MMA(d, a, b0, b1) \
    asm volatile("mma.sync.aligned.m16n8k16.row.col.f32.bf16.bf16.f32 " \
        "{%0,%1,%2,%3},{%4,%5,%6,%7},{%8,%9},{%0,%1,%2,%3};" \
        : "+f"((d)[0]), "+f"((d)[1]), "+f"((d)[2]), "+f"((d)[3]) \
        : "r"((a)[0]), "r"((a)[1]), "r"((a)[2]), "r"((a)[3]), "r"(b0), "r"(b1))

__device__ __forceinline__ void bsplit(float v, unsigned short& h, unsigned short& l) {
    __nv_bfloat16 bh = __float2bfloat16(v);
    __nv_bfloat16 bl = __float2bfloat16(v - __bfloat162float(bh));
    h = *(unsigned short*)&bh; l = *(unsigned short*)&bl;
}

// ---------------- prep kernels ----------------
// Per h-tile c: smem rows k 0..1023 of 64B (32 n-cols).
// n decode: u2=n>>4 (warp-half), u=(n>>3)&1, q=(n>>1)&3, s=n&1 -> gate=2u+s, j=u2*4+q.
__global__ void pack_w(const float* __restrict__ Wi, const float* __restrict__ Wh) {
    int c = blockIdx.x;
    unsigned char* base = g_wt + (size_t)c * 131072;
    for (int e = threadIdx.x; e < 32768; e += 256) {
        int k = e >> 5, n = e & 31;
        int g = 2 * ((n >> 3) & 1) + (n & 1);
        int j = (n >> 4) * 4 + ((n >> 1) & 3);
        int col = g * 512 + c * 8 + j;
        float v = (k < 512) ? Wi[k * 2048 + col] : Wh[(k - 512) * 2048 + col];
        unsigned short h, l; bsplit(v, h, l);
        int off = k * 64 + ((((n >> 3)) ^ ((k >> 1) & 3)) << 4) + ((n & 7) << 1);
        *(unsigned short*)(base + off) = h;
        *(unsigned short*)(base + 65536 + off) = l;
    }
}
__global__ void conv_obs(const float* __restrict__ obs) {
    size_t g = (size_t)blockIdx.x * 256 + threadIdx.x;   // 16,777,216
    int d4 = (int)(g & 127); size_t bt = g >> 7;
    int b = (int)(bt >> 10), t = (int)(bt & 1023);
    float4 v = *(const float4*)&obs[(((size_t)b * 1024 + t) * 512) + d4 * 4];
    unsigned short h0,h1,h2,h3,l0,l1,l2,l3;
    bsplit(v.x,h0,l0); bsplit(v.y,h1,l1); bsplit(v.z,h2,l2); bsplit(v.w,h3,l3);
    size_t o = ((size_t)t * 128 + b) * 512 + d4 * 4;
    *(ushort4*)&g_obs_hi[o] = make_ushort4(h0,h1,h2,h3);
    *(ushort4*)&g_obs_lo[o] = make_ushort4(l0,l1,l2,l3);
}
__global__ void pack_h0(const float* __restrict__ h0p) {
    int g = blockIdx.x * 256 + threadIdx.x;  // 65536
    unsigned short h, l; bsplit(h0p[g], h, l);
    g_hh[0][g] = h; g_hl[0][g] = l;
}

// ---------------- recurrent kernel ----------------
// stage A chunk [64 rows][64 k] bf16 hi+lo (8KB+8KB) into one of 4 buffers
__device__ __forceinline__ void stage_chunk(uint32_t dst, int row0, int t, int ch, int tid) {
    const unsigned short *bh, *bl; int koff;
    if (ch < 8) { bh = g_obs_hi + (size_t)t * 65536; bl = g_obs_lo + (size_t)t * 65536; koff = ch * 64; }
    else        { int p = t & 1; bh = g_hh[p]; bl = g_hl[p]; koff = (ch - 8) * 64; }
    #pragma unroll
    for (int i = 0; i < 2; i++) {
        int g = i * 256 + tid; int r = g >> 3, seg = g & 7;
        uint32_t d = dst + SWZ(r * 128 + seg * 16);
        const unsigned short* s = bh + (size_t)(row0 + r) * 512 + koff + seg * 8;
        CPA(d, s);
        CPA(d + 8192, bl + (size_t)(row0 + r) * 512 + koff + seg * 8);
    }
}

__global__ void __launch_bounds__(256, 1) lstm_rec(
    const float* __restrict__ bv, const float* __restrict__ c0,
    float* __restrict__ out, int out_size)
{
    extern __shared__ char sm[];  // [W hi 64K | lo 64K][A: 4 bufs x (hi 8K + lo 8K)]
    const int tid = threadIdx.x, warp = tid >> 5, lane = tid & 31;
    const int bi = blockIdx.x >> 6, hj = blockIdx.x & 63;
    const int row0 = bi * 64, hc0 = hj * 8;
    const uint32_t smW = smem_u32(sm), smA = smW + 131072;

    // load resident W (128KB)
    const unsigned char* wsrc = g_wt + (size_t)hj * 131072;
    for (int i = tid; i < 8192; i += 256) CPA(smW + i * 16, wsrc + i * 16);
    CPCOMMIT(); CPWAIT(0);
    __syncthreads();

    // warp tile: rows m0..m0+15, n-half wn (16 cols); thread owns 2 (b,h) elems, all 4 gates
    const int wr = warp & 3, wn = warp >> 2;
    const int m0 = wr * 16;
    const int q = lane & 3;
    const int j = wn * 4 + q;                 // h col within tile
    const int rA = row0 + m0 + (lane >> 2);   // global batch row (and rA+8)
    float b_i = bv[0 * 512 + hc0 + j], b_f = bv[1 * 512 + hc0 + j];
    float b_g = bv[2 * 512 + hc0 + j], b_o = bv[3 * 512 + hc0 + j];
    float cs0 = c0[(size_t)rA * 512 + hc0 + j];
    float cs1 = c0[(size_t)(rA + 8) * 512 + hc0 + j];

    stage_chunk(smA,         row0, 0, 0, tid); CPCOMMIT();
    stage_chunk(smA + 16384, row0, 0, 1, tid); CPCOMMIT();

    const int arow = m0 + (lane & 15);
    const int hseg = (lane >> 4) * 16;
    const int brow_l = lane & 15;
    const int bgsel = lane >> 4;

    for (int t = 0; t < 1024; t++) {
        float acc0[4] = {0.f, 0.f, 0.f, 0.f};   // gates i,f
        float acc1[4] = {0.f, 0.f, 0.f, 0.f};   // gates g,o

        for (int ch = 0; ch < 16; ch++) {
            CPWAIT(1);
            __syncthreads();
            // prefetch chunk ch+2 into buf (ch+2)&3 (readers done since sync of iter ch-1)
            int ch2 = ch + 2, t2 = t;
            if (ch2 > 15) { ch2 -= 16; t2++; }
            if (t2 < 1024) stage_chunk(smA + ((ch + 2) & 3) * 16384, row0, t2, ch2, tid);
            CPCOMMIT();
            // MMA on buf ch&3
            const uint32_t Ah = smA + (ch & 3) * 16384, Al = Ah + 8192;
            #pragma unroll
            for (int ks = 0; ks < 4; ks++) {
                uint32_t ah[4], al[4], bh[4], bl[4];
                uint32_t aoff = SWZ(arow * 128 + ks * 32 + hseg);
                LDM4(ah, Ah + aoff);
                LDM4(al, Al + aoff);
                int krow = ch * 64 + ks * 16 + brow_l;
                uint32_t bsw = (krow >> 1) & 3;
                uint32_t ba = smW + krow * 64 + (((wn * 2 + bgsel) ^ bsw) << 4);
                LDM4T(bh, ba);
                LDM4T(bl, ba + 65536);
                MMA(acc0, ah, bh[0], bh[1]); MMA(acc1, ah, bh[2], bh[3]);
                MMA(acc0, ah, bl[0], bl[1]); MMA(acc1, ah, bl[2], bl[3]);
                MMA(acc0, al, bh[0], bh[1]); MMA(acc1, al, bh[2], bh[3]);
            }
        }

        // epilogue: register-local gates (acc0 = i,f ; acc1 = g,o)
        const int pn = (t + 1) & 1;
        #pragma unroll
        for (int rh = 0; rh < 2; rh++) {
            const int r = rA + rh * 8;
            float iv = acc0[2 * rh + 0] + b_i;
            float fv = acc0[2 * rh + 1] + b_f;
            float gv = acc1[2 * rh + 0] + b_g;
            float ov = acc1[2 * rh + 1] + b_o;
            float si = 1.f / (1.f + __expf(-iv));
            float sf = 1.f / (1.f + __expf(-fv));
            float so = 1.f / (1.f + __expf(-ov));
            float tg = 1.f - 2.f / (__expf(2.f * gv) + 1.f);
            float cn = sf * (rh ? cs1 : cs0) + si * tg;
            if (rh) cs1 = cn; else cs0 = cn;
            float tc = 1.f - 2.f / (__expf(2.f * cn) + 1.f);
            float hv = so * tc;
            out[((size_t)r * 1024 + t) * 512 + hc0 + j] = hv;
            unsigned short hb, lb; bsplit(hv, hb, lb);
            g_hh[pn][r * 512 + hc0 + j] = hb;
            g_hl[pn][r * 512 + hc0 + j] = lb;
            if (t == 1023 && out_size >= 67108864 + 131072) {
                out[67108864 + r * 512 + hc0 + j] = cn;
                out[67108864 + 65536 + r * 512 + hc0 + j] = hv;
            }
        }

        // device-wide sense-reversal barrier (128 CTAs)
        __threadfence();
        __syncthreads();
        if (tid == 0) {
            const unsigned target = (unsigned)((t & 1) ^ 1);
            if (atomicAdd(&g_count, 1u) == 127) {
                g_count = 0; __threadfence(); g_sense = target;
            } else {
                while (g_sense != target) { } __threadfence();
            }
        }
        __syncthreads();
    }
}

extern "C" void kernel_launch(void* const* d_in, const int* in_sizes, int n_in,
                              void* d_out, int out_size)
{
    const float* obs = (const float*)d_in[0];
    const float* Wi  = (const float*)d_in[1];
    const float* Wh  = (const float*)d_in[2];
    const float* bv  = (const float*)d_in[3];
    const float* c0  = (const float*)d_in[4];
    const float* h0  = (const float*)d_in[5];

    pack_w<<<64, 256>>>(Wi, Wh);
    conv_obs<<<65536, 256>>>(obs);
    pack_h0<<<256, 256>>>(h0);

    const int smem = 196608;  // 128K W + 64K A (4 buffers)
    cudaFuncSetAttribute(lstm_rec, cudaFuncAttributeMaxDynamicSharedMemorySize, smem);
    lstm_rec<<<128, 256, smem>>>(bv, c0, (float*)d_out, out_size);
}